// round 8
// baseline (speedup 1.0000x reference)
#include <cuda_runtime.h>
#include <cuda_bf16.h>
#include <stdint.h>
#include <math.h>

// NetVLAD via mma.sync bf16, register softmax with FFMA-only exp (no MUFU).
// x [64,128,4800], conv_w [64,128], centroids [64,128], out [64,8192].

#define Nn 64
#define Dd 128
#define Pp 4800
#define Kk 64
#define PT 128
#define NT 38
#define SPLIT 4

#define SB 136      // bf16 row stride (elements); 272B rows

#define OFF_DP   0        // bf16 x[d][p] [128][136] = 34816
#define OFF_W    34816    // bf16 w[k][d] [64][136]  = 17408
#define OFF_SA   52224    // bf16 sa'[k][p] [64][136] = 17408
#define OFF_SSP  69632    // fp32 [8][128] partial ssq = 4096 (reused as ssw[8][64])
#define OFF_RINV 73728    // 128 f32
#define SMEM_TOTAL 74240

__device__ float g_aggp[Nn * SPLIT * Kk * Dd];   // per-(n,s) slabs [d][k]
__device__ float g_ssump[Nn * SPLIT * Kk];

static __device__ __forceinline__ uint32_t smem_u32(const void* p) {
    uint32_t a;
    asm("{ .reg .u64 t; cvta.to.shared.u64 t, %1; cvt.u32.u64 %0, t; }" : "=r"(a) : "l"(p));
    return a;
}
static __device__ __forceinline__ void ldm4(unsigned r[4], uint32_t addr) {
    asm volatile("ldmatrix.sync.aligned.m8n8.x4.shared.b16 {%0,%1,%2,%3}, [%4];"
        : "=r"(r[0]), "=r"(r[1]), "=r"(r[2]), "=r"(r[3]) : "r"(addr));
}
static __device__ __forceinline__ void ldm4t(unsigned r[4], uint32_t addr) {
    asm volatile("ldmatrix.sync.aligned.m8n8.x4.trans.shared.b16 {%0,%1,%2,%3}, [%4];"
        : "=r"(r[0]), "=r"(r[1]), "=r"(r[2]), "=r"(r[3]) : "r"(addr));
}
static __device__ __forceinline__ void mma_bf16(float c[4], const unsigned a[4],
                                                unsigned b0, unsigned b1) {
    asm volatile("mma.sync.aligned.m16n8k16.row.col.f32.bf16.bf16.f32 "
        "{%0,%1,%2,%3}, {%4,%5,%6,%7}, {%8,%9}, {%0,%1,%2,%3};"
        : "+f"(c[0]), "+f"(c[1]), "+f"(c[2]), "+f"(c[3])
        : "r"(a[0]), "r"(a[1]), "r"(a[2]), "r"(a[3]), "r"(b0), "r"(b1));
}

// FFMA-only exp: e = 2^(t*rvL2E), t*rvL2E in ~[-2,2]. No MUFU.
// fn = t*rvL + MAGIC; g = fn - MAGIC; f = t*rvL - g in [-0.5,0.5];
// 2^f by degree-5 poly; exponent spliced via int add (bits(fn)<<23 == n<<23).
#define EXP_MAGIC 12582912.0f
static __device__ __forceinline__ float fast_exp2_scaled(float t, float rvL) {
    float fn = fmaf(t, rvL, EXP_MAGIC);
    float g  = fn - EXP_MAGIC;
    float f  = fmaf(t, rvL, -g);
    float p  = fmaf(f, 0.00133335581464f, 0.00961812910763f);
    p = fmaf(p, f, 0.0555041086648f);
    p = fmaf(p, f, 0.240226506959f);
    p = fmaf(p, f, 0.69314718056f);
    p = fmaf(p, f, 1.0f);
    return __int_as_float(__float_as_int(p) + (__float_as_int(fn) << 23));
}

// ---------------------------------------------------------------------------
__global__ __launch_bounds__(256, 2)
void netvlad_main_kernel(const float* __restrict__ x, const float* __restrict__ w) {
    extern __shared__ char sm[];
    const uint32_t sb = smem_u32(sm);
    const int tid = threadIdx.x;
    const int wid = tid >> 5;
    const int lid = tid & 31;
    const int n = blockIdx.y;
    const int s = blockIdx.x;

    const unsigned lane15 = lid & 15, laneh = lid >> 4;
    const unsigned lane7  = lid & 7,  lane8h = (lid >> 3) & 1;
    const int g = lid >> 2, tq = lid & 3;

    float* ssp  = reinterpret_cast<float*>(sm + OFF_SSP);
    float* rinv = reinterpret_cast<float*>(sm + OFF_RINV);

    // stage conv_w -> bf16 [k][d]
    for (int i = tid; i < 2048; i += 256) {
        int k = i >> 5, d4 = (i & 31) << 2;
        float4 v = *reinterpret_cast<const float4*>(w + k * Dd + d4);
        __nv_bfloat162 h0 = __floats2bfloat162_rn(v.x, v.y);
        __nv_bfloat162 h1 = __floats2bfloat162_rn(v.z, v.w);
        uint2 u = make_uint2(*reinterpret_cast<uint32_t*>(&h0),
                             *reinterpret_cast<uint32_t*>(&h1));
        *reinterpret_cast<uint2*>(sm + OFF_W + (uint32_t)(k * SB + d4) * 2) = u;
    }

    const int pbase = wid * 16;                               // GEMM1 warp p-tile
    const int mw2 = (wid >> 1) * 32, nw2 = (wid & 1) * 32;    // GEMM2: d x k
    float C2[8][4];
#pragma unroll
    for (int i = 0; i < 8; i++)
#pragma unroll
        for (int j = 0; j < 4; j++) C2[i][j] = 0.f;
    float ssum_reg[8];
#pragma unroll
    for (int i = 0; i < 8; i++) ssum_reg[i] = 0.f;

    const float* xn = x + (size_t)n * Dd * Pp;
    const int myp4 = (lid << 2);        // phase1 pixel group (4 pixels)

    for (int t = s; t < NT; t += SPLIT) {
        const int p0 = t * PT;
        __syncthreads();   // DP/SA consumed by previous iteration's GEMM2

        // --- phase1: gmem fp32 -> bf16 DP [d][p]; fused ssq partials ---
        {
            float4 sq = make_float4(0.f, 0.f, 0.f, 0.f);
#pragma unroll
            for (int i = 0; i < 16; i++) {
                int d = wid + 8 * i;
                float4 v = make_float4(0.f, 0.f, 0.f, 0.f);
                if (p0 + myp4 < Pp)
                    v = *reinterpret_cast<const float4*>(xn + (size_t)d * Pp + p0 + myp4);
                sq.x += v.x * v.x; sq.y += v.y * v.y;
                sq.z += v.z * v.z; sq.w += v.w * v.w;
                __nv_bfloat162 h0 = __floats2bfloat162_rn(v.x, v.y);
                __nv_bfloat162 h1 = __floats2bfloat162_rn(v.z, v.w);
                uint2 u = make_uint2(*reinterpret_cast<uint32_t*>(&h0),
                                     *reinterpret_cast<uint32_t*>(&h1));
                *reinterpret_cast<uint2*>(sm + OFF_DP + (uint32_t)(d * SB + myp4) * 2) = u;
            }
            *reinterpret_cast<float4*>(&ssp[wid * 128 + myp4]) = sq;
        }
        __syncthreads();
        if (tid < 128) {
            float ss = 0.f;
#pragma unroll
            for (int wI = 0; wI < 8; wI++) ss += ssp[wI * 128 + tid];
            rinv[tid] = 1.f / fmaxf(sqrtf(ss), 1e-12f);
        }
        __syncthreads();

        // --- GEMM1 (warp: 64k x 16p) + register softmax -> sa' ---
        {
            float C1[8][4];
#pragma unroll
            for (int i = 0; i < 8; i++)
#pragma unroll
                for (int j = 0; j < 4; j++) C1[i][j] = 0.f;
#pragma unroll
            for (int d0 = 0; d0 < 128; d0 += 16) {
                unsigned a[4][4], bb[4];
#pragma unroll
                for (int fk = 0; fk < 4; fk++)
                    ldm4(a[fk], sb + OFF_W +
                        (uint32_t)((16 * fk + lane15) * SB + d0 + 8 * laneh) * 2);
                ldm4t(bb, sb + OFF_DP + (uint32_t)(
                    (d0 + 8 * lane8h + lane7) * SB + pbase + 8 * laneh) * 2);
#pragma unroll
                for (int fk = 0; fk < 4; fk++)
#pragma unroll
                    for (int fp = 0; fp < 2; fp++)
                        mma_bf16(C1[fk * 2 + fp], a[fk], bb[fp * 2], bb[fp * 2 + 1]);
            }

            // rinv per column; fold log2(e) into exp's leading FFMA
            float rv[2][2], rvL[2][2];
            {
                float2 r0 = *reinterpret_cast<const float2*>(&rinv[pbase + 2 * tq]);
                float2 r1 = *reinterpret_cast<const float2*>(&rinv[pbase + 8 + 2 * tq]);
                rv[0][0] = r0.x; rv[0][1] = r0.y; rv[1][0] = r1.x; rv[1][1] = r1.y;
            }
#pragma unroll
            for (int fp = 0; fp < 2; fp++)
#pragma unroll
                for (int c = 0; c < 2; c++)
                    rvL[fp][c] = rv[fp][c] * 1.4426950408889634f;

            // exp (no max-subtract: |logit*rinv| <= ~1.4, safe) + column sums
            float sumc[2][2] = {{0.f, 0.f}, {0.f, 0.f}};
#pragma unroll
            for (int fk = 0; fk < 4; fk++)
#pragma unroll
                for (int fp = 0; fp < 2; fp++)
#pragma unroll
                    for (int h = 0; h < 2; h++)
#pragma unroll
                        for (int c = 0; c < 2; c++) {
                            float e = fast_exp2_scaled(C1[fk * 2 + fp][2 * h + c],
                                                       rvL[fp][c]);
                            C1[fk * 2 + fp][2 * h + c] = e;
                            sumc[fp][c] += e;
                        }
#pragma unroll
            for (int fp = 0; fp < 2; fp++)
#pragma unroll
                for (int c = 0; c < 2; c++) {
                    float su = sumc[fp][c];
                    su += __shfl_xor_sync(0xffffffffu, su, 4);
                    su += __shfl_xor_sync(0xffffffffu, su, 8);
                    su += __shfl_xor_sync(0xffffffffu, su, 16);
                    sumc[fp][c] = su;
                }
            // inv sums with validity mask
            float isum[2][2];
#pragma unroll
            for (int fp = 0; fp < 2; fp++)
#pragma unroll
                for (int c = 0; c < 2; c++) {
                    int p = pbase + 8 * fp + 2 * tq + c;
                    isum[fp][c] = (p0 + p < Pp) ? (1.f / sumc[fp][c]) : 0.f;
                }
            // ssum accumulate + write sa' = softmax * rinv (paired bf16 stores)
#pragma unroll
            for (int fk = 0; fk < 4; fk++)
#pragma unroll
                for (int h = 0; h < 2; h++) {
                    int k = 16 * fk + 8 * h + g;
#pragma unroll
                    for (int fp = 0; fp < 2; fp++) {
                        float s0 = C1[fk * 2 + fp][2 * h + 0] * isum[fp][0];
                        float s1 = C1[fk * 2 + fp][2 * h + 1] * isum[fp][1];
                        ssum_reg[2 * fk + h] += s0 + s1;
                        __nv_bfloat162 hb =
                            __floats2bfloat162_rn(s0 * rv[fp][0], s1 * rv[fp][1]);
                        *reinterpret_cast<uint32_t*>(sm + OFF_SA +
                            (uint32_t)(k * SB + pbase + 8 * fp + 2 * tq) * 2) =
                            *reinterpret_cast<uint32_t*>(&hb);
                    }
                }
        }
        __syncthreads();

        // --- GEMM2: agg[d][k] += x[d][p] * sa'[k][p]^T ---
#pragma unroll
        for (int pc = 0; pc < 128; pc += 16) {
            unsigned a[2][4], bb[2][4];
            ldm4(a[0], sb + OFF_DP + (uint32_t)((mw2 + 0  + lane15) * SB + pc + 8 * laneh) * 2);
            ldm4(a[1], sb + OFF_DP + (uint32_t)((mw2 + 16 + lane15) * SB + pc + 8 * laneh) * 2);
#pragma unroll
            for (int bp = 0; bp < 2; bp++)
                ldm4(bb[bp], sb + OFF_SA + (uint32_t)(
                    (nw2 + (2 * bp + (int)laneh) * 8 + (int)lane7) * SB
                    + pc + 8 * lane8h) * 2);
#pragma unroll
            for (int f = 0; f < 2; f++)
#pragma unroll
                for (int ff = 0; ff < 4; ff++)
                    mma_bf16(C2[f * 4 + ff], a[f],
                             bb[ff >> 1][(ff & 1) * 2], bb[ff >> 1][(ff & 1) * 2 + 1]);
        }
    }

    // --- epilogue: slab [d][k] (plain STG) ---
    {
        float* slab = g_aggp + ((size_t)(n * SPLIT + s) << 13);
#pragma unroll
        for (int f = 0; f < 2; f++)
#pragma unroll
            for (int ff = 0; ff < 4; ff++) {
                int d = mw2 + f * 16 + g;
                int kb = nw2 + ff * 8 + 2 * tq;
                *reinterpret_cast<float2*>(&slab[d * Kk + kb]) =
                    make_float2(C2[f * 4 + ff][0], C2[f * 4 + ff][1]);
                *reinterpret_cast<float2*>(&slab[(d + 8) * Kk + kb]) =
                    make_float2(C2[f * 4 + ff][2], C2[f * 4 + ff][3]);
            }
    }
    // --- ssum: reduce over tq lanes, then across warps via smem ---
    __syncthreads();
#pragma unroll
    for (int m = 0; m < 8; m++) {
        ssum_reg[m] += __shfl_xor_sync(0xffffffffu, ssum_reg[m], 1);
        ssum_reg[m] += __shfl_xor_sync(0xffffffffu, ssum_reg[m], 2);
    }
    if (tq == 0) {
#pragma unroll
        for (int m = 0; m < 8; m++)
            ssp[wid * 64 + 8 * m + g] = ssum_reg[m];   // reuse ssp as [8][64]
    }
    __syncthreads();
    if (tid < Kk) {
        float ssk = 0.f;
#pragma unroll
        for (int wI = 0; wI < 8; wI++) ssk += ssp[wI * 64 + tid];
        g_ssump[(n * SPLIT + s) * Kk + tid] = ssk;
    }
}

// ---------------------------------------------------------------------------
// Finalize: grid = Nn, block = 1024.
__global__ __launch_bounds__(1024)
void netvlad_finalize_kernel(const float* __restrict__ cent, float* __restrict__ out) {
    __shared__ float stage[128 * 65];
    __shared__ float sred[64];
    __shared__ float stot;
    const int n = blockIdx.x, tid = threadIdx.x;

    const float* base = g_aggp + ((size_t)n * SPLIT << 13);
#pragma unroll
    for (int c = 0; c < 2; c++) {
        int idx = (tid + 1024 * c) * 4;
        float4 a = *reinterpret_cast<const float4*>(base + idx);
#pragma unroll
        for (int s2 = 1; s2 < SPLIT; s2++) {
            float4 b = *reinterpret_cast<const float4*>(base + (s2 << 13) + idx);
            a.x += b.x; a.y += b.y; a.z += b.z; a.w += b.w;
        }
        int d = idx >> 6, k = idx & 63;
        stage[d * 65 + k + 0] = a.x;
        stage[d * 65 + k + 1] = a.y;
        stage[d * 65 + k + 2] = a.z;
        stage[d * 65 + k + 3] = a.w;
    }
    __syncthreads();

    const int k = tid >> 4, part = tid & 15, dbase = part * 8;
    float ssk = 0.f;
#pragma unroll
    for (int s2 = 0; s2 < SPLIT; s2++)
        ssk += g_ssump[(n * SPLIT + s2) * Kk + k];

    float v[8];
    float ssq = 0.f;
#pragma unroll
    for (int q = 0; q < 2; q++) {
        float4 c = *reinterpret_cast<const float4*>(&cent[k * Dd + dbase + 4 * q]);
        float v0 = stage[(dbase + 4 * q + 0) * 65 + k] - ssk * c.x;
        float v1 = stage[(dbase + 4 * q + 1) * 65 + k] - ssk * c.y;
        float v2 = stage[(dbase + 4 * q + 2) * 65 + k] - ssk * c.z;
        float v3 = stage[(dbase + 4 * q + 3) * 65 + k] - ssk * c.w;
        v[4*q+0] = v0; v[4*q+1] = v1; v[4*q+2] = v2; v[4*q+3] = v3;
        ssq += v0*v0 + v1*v1 + v2*v2 + v3*v3;
    }
#pragma unroll
    for (int o = 1; o < 16; o <<= 1)
        ssq += __shfl_xor_sync(0xffffffffu, ssq, o);
    const float rin = 1.f / fmaxf(sqrtf(ssq), 1e-12f);

    if (part == 0) sred[k] = ssq * rin * rin;
    __syncthreads();
    if (tid < 32) {
        float v2 = sred[tid] + sred[tid + 32];
#pragma unroll
        for (int o = 16; o > 0; o >>= 1) v2 += __shfl_xor_sync(0xffffffffu, v2, o);
        if (tid == 0) stot = v2;
    }
    __syncthreads();
    const float rg = 1.f / fmaxf(sqrtf(stot), 1e-12f);
    const float sc = rin * rg;

    float* op = out + (size_t)n * Kk * Dd + k * Dd + dbase;
#pragma unroll
    for (int q = 0; q < 2; q++) {
        float4 o;
        o.x = v[4*q+0]*sc; o.y = v[4*q+1]*sc; o.z = v[4*q+2]*sc; o.w = v[4*q+3]*sc;
        *reinterpret_cast<float4*>(op + 4 * q) = o;
    }
}

// ---------------------------------------------------------------------------
extern "C" void kernel_launch(void* const* d_in, const int* in_sizes, int n_in,
                              void* d_out, int out_size) {
    const float* x    = (const float*)d_in[0];
    const float* w    = (const float*)d_in[1];
    const float* cent = (const float*)d_in[2];
    float* out = (float*)d_out;

    cudaFuncSetAttribute(netvlad_main_kernel,
                         cudaFuncAttributeMaxDynamicSharedMemorySize, SMEM_TOTAL);
    netvlad_main_kernel<<<dim3(SPLIT, Nn), 256, SMEM_TOTAL>>>(x, w);
    netvlad_finalize_kernel<<<Nn, 1024>>>(cent, out);
}